// round 13
// baseline (speedup 1.0000x reference)
#include <cuda_runtime.h>

// Noisy LIF spiking neuron scan — R11: v8 ops + CH=2 front-batched loads.
//   u = 0.5*u + x[t] - 0.5*noise[t] ; o = (u > 1) ; u = o ? 0 : u
//
// R7 record: plain v8, tpb=256, 512 CTAs -> DRAM=84.8%, ncu 114.2us.
// Occupancy there is THREAD-limited (886 threads/SM, 40.5%), not
// reg-limited: regs can grow to ~73 for free. So unlike the float4 rounds
// (where CH-batching cost occupancy and lost), batching 2 timesteps of v8
// loads (4 independent 32B loads in flight per thread) doubles per-SM
// outstanding load wavefronts at zero occupancy cost.

static constexpr int B  = 16;
static constexpr int T  = 64;
static constexpr int N  = 65536;
static constexpr int N8 = N / 8;     // float8 lanes per (b, t) row = 8192

__device__ __forceinline__ void ldg256(const float* p, float* v) {
    asm volatile(
        "ld.global.v8.f32 {%0, %1, %2, %3, %4, %5, %6, %7}, [%8];"
        : "=f"(v[0]), "=f"(v[1]), "=f"(v[2]), "=f"(v[3]),
          "=f"(v[4]), "=f"(v[5]), "=f"(v[6]), "=f"(v[7])
        : "l"(p));
}

__device__ __forceinline__ void stg256(float* p, const float* v) {
    asm volatile(
        "st.global.v8.f32 [%0], {%1, %2, %3, %4, %5, %6, %7, %8};"
        :: "l"(p),
           "f"(v[0]), "f"(v[1]), "f"(v[2]), "f"(v[3]),
           "f"(v[4]), "f"(v[5]), "f"(v[6]), "f"(v[7])
        : "memory");
}

__global__ __launch_bounds__(256) void lif_kernel(
    const float* __restrict__ x,
    const float* __restrict__ noise,
    float* __restrict__ out)
{
    int idx = blockIdx.x * blockDim.x + threadIdx.x;   // 0 .. B*N8-1 (exact)

    int b  = idx >> 13;          // / N8 (8192)
    int n8 = idx & (N8 - 1);     // % N8

    const size_t base = (size_t)b * T * N + (size_t)n8 * 8;
    const float* __restrict__ xp = x     + base;
    const float* __restrict__ np = noise + base;
    float*       __restrict__ op = out   + base;

    float u[8];
#pragma unroll
    for (int i = 0; i < 8; i++) u[i] = 0.f;

#pragma unroll
    for (int t0 = 0; t0 < T; t0 += 2) {
        float xv0[8], nv0[8], xv1[8], nv1[8];

        // Front-batch: 4 independent 256-bit loads (128 B in flight/thread).
        ldg256(xp + (size_t)(t0 + 0) * N, xv0);
        ldg256(np + (size_t)(t0 + 0) * N, nv0);
        ldg256(xp + (size_t)(t0 + 1) * N, xv1);
        ldg256(np + (size_t)(t0 + 1) * N, nv1);

        float o0[8], o1[8];
#pragma unroll
        for (int i = 0; i < 8; i++) {
            u[i]  = fmaf(-0.5f, nv0[i], fmaf(0.5f, u[i], xv0[i]));
            o0[i] = (u[i] > 1.0f) ? 1.0f : 0.0f;
            u[i]  = (u[i] > 1.0f) ? 0.0f : u[i];

            u[i]  = fmaf(-0.5f, nv1[i], fmaf(0.5f, u[i], xv1[i]));
            o1[i] = (u[i] > 1.0f) ? 1.0f : 0.0f;
            u[i]  = (u[i] > 1.0f) ? 0.0f : u[i];
        }

        stg256(op + (size_t)(t0 + 0) * N, o0);
        stg256(op + (size_t)(t0 + 1) * N, o1);
    }
}

extern "C" void kernel_launch(void* const* d_in, const int* in_sizes, int n_in,
                              void* d_out, int out_size)
{
    const float* x     = (const float*)d_in[0];
    const float* noise = (const float*)d_in[1];
    float*       out   = (float*)d_out;

    const int total_threads = B * N8;        // 131072
    const int tpb = 256;
    const int blocks = total_threads / tpb;  // 512, exact

    lif_kernel<<<blocks, tpb>>>(x, noise, out);
}

// round 14
// speedup vs baseline: 1.0090x; 1.0090x over previous
#include <cuda_runtime.h>

// Noisy LIF spiking neuron scan — FINAL (R7 config, measured optimum).
//   u = 0.5*u + x[t] - 0.5*noise[t] ; o = (u > 1) ; u = o ? 0 : u
//
// Surface exhaustively mapped over 11 benches (768 MB irreducible traffic):
//   vector width 128b->256b: +0.7% DRAM (only win)
//   per-thread load batching: loses even at zero occupancy cost (R11:
//     regs 40->64, occ flat, DRAM 84.8->83.9) -> bottleneck is the DRAM
//     scheduler's ~85%-of-spec efficiency on a 2:1 R/W stream, not request
//     supply. Cache hints (.cs/.wt), prefetch pipelines, grid reshapes:
//     all strictly worse. T-parallel scan adds >=17% traffic for
//     unconvertible occupancy -> ruled out analytically.
// Record: DRAM=84.8%, ncu 114.2us, 6.72 TB/s. One thread owns 8 adjacent
// lanes via ld/st.global.v8.f32; 131072 threads, 512 CTAs x 256, regs=40.

static constexpr int B  = 16;
static constexpr int T  = 64;
static constexpr int N  = 65536;
static constexpr int N8 = N / 8;     // float8 lanes per (b, t) row = 8192

__device__ __forceinline__ void ldg256(const float* p, float* v) {
    asm volatile(
        "ld.global.v8.f32 {%0, %1, %2, %3, %4, %5, %6, %7}, [%8];"
        : "=f"(v[0]), "=f"(v[1]), "=f"(v[2]), "=f"(v[3]),
          "=f"(v[4]), "=f"(v[5]), "=f"(v[6]), "=f"(v[7])
        : "l"(p));
}

__device__ __forceinline__ void stg256(float* p, const float* v) {
    asm volatile(
        "st.global.v8.f32 [%0], {%1, %2, %3, %4, %5, %6, %7, %8};"
        :: "l"(p),
           "f"(v[0]), "f"(v[1]), "f"(v[2]), "f"(v[3]),
           "f"(v[4]), "f"(v[5]), "f"(v[6]), "f"(v[7])
        : "memory");
}

__global__ __launch_bounds__(256) void lif_kernel(
    const float* __restrict__ x,
    const float* __restrict__ noise,
    float* __restrict__ out)
{
    int idx = blockIdx.x * blockDim.x + threadIdx.x;   // 0 .. B*N8-1 (exact)

    int b  = idx >> 13;          // / N8 (8192)
    int n8 = idx & (N8 - 1);     // % N8

    const size_t base = (size_t)b * T * N + (size_t)n8 * 8;
    const float* __restrict__ xp = x     + base;
    const float* __restrict__ np = noise + base;
    float*       __restrict__ op = out   + base;

    float u[8];
#pragma unroll
    for (int i = 0; i < 8; i++) u[i] = 0.f;

#pragma unroll
    for (int t = 0; t < T; t++) {
        float xv[8], nv[8], o[8];
        ldg256(xp + (size_t)t * N, xv);
        ldg256(np + (size_t)t * N, nv);

#pragma unroll
        for (int i = 0; i < 8; i++) {
            u[i] = fmaf(-0.5f, nv[i], fmaf(0.5f, u[i], xv[i]));
            o[i] = (u[i] > 1.0f) ? 1.0f : 0.0f;
            u[i] = (u[i] > 1.0f) ? 0.0f : u[i];
        }

        stg256(op + (size_t)t * N, o);
    }
}

extern "C" void kernel_launch(void* const* d_in, const int* in_sizes, int n_in,
                              void* d_out, int out_size)
{
    const float* x     = (const float*)d_in[0];
    const float* noise = (const float*)d_in[1];
    float*       out   = (float*)d_out;

    const int total_threads = B * N8;        // 131072
    const int tpb = 256;
    const int blocks = total_threads / tpb;  // 512, exact

    lif_kernel<<<blocks, tpb>>>(x, noise, out);
}

// round 16
// speedup vs baseline: 1.0430x; 1.0337x over previous
#include <cuda_runtime.h>

// Noisy LIF spiking neuron scan — R13: exact resubmission of R2 (timed-record
// config, 123.4us) to test reproducibility of its timed result.
//   u = 0.5*u + x[t] - 0.5*noise[t] ; o = (u > 1) ; u = o ? 0 : u
//
// Context: ncu-side the surface is exhausted (best 84.8% DRAM, all configs
// >=83% within the measured +/-1.9pt run noise). R2 is the only config that
// ever timed under 125us (123.4, one sample; all others 127-130 over ten
// runs) and the only one with a ~6us timed-vs-ncu offset instead of ~12us.
// This round distinguishes single-sample luck from a real replay-regime
// advantage of its burst-batched load pattern. Scored metric is timed dur.

static constexpr int B  = 16;
static constexpr int T  = 64;
static constexpr int N  = 65536;
static constexpr int N4 = N / 4;     // float4 lanes per (b, t) row
static constexpr int CH = 4;         // timesteps per load batch

__global__ __launch_bounds__(128) void lif_kernel(
    const float4* __restrict__ x,
    const float4* __restrict__ noise,
    float4* __restrict__ out)
{
    int idx = blockIdx.x * blockDim.x + threadIdx.x;   // 0 .. B*N4-1
    if (idx >= B * N4) return;

    int b  = idx / N4;
    int n4 = idx % N4;

    const size_t base = (size_t)b * T * N4 + n4;
    const float4* __restrict__ xp = x     + base;
    const float4* __restrict__ np = noise + base;
    float4*       __restrict__ op = out   + base;

    float ux = 0.f, uy = 0.f, uz = 0.f, uw = 0.f;

#pragma unroll
    for (int t0 = 0; t0 < T; t0 += CH) {
        float4 xv[CH], nv[CH];

        // Front-batch all loads for this chunk: 2*CH independent LDG.128.
#pragma unroll
        for (int j = 0; j < CH; j++) {
            xv[j] = __ldcs(xp + (t0 + j) * N4);
            nv[j] = __ldcs(np + (t0 + j) * N4);
        }

#pragma unroll
        for (int j = 0; j < CH; j++) {
            float4 o;

            ux  = fmaf(0.5f, ux, xv[j].x) - 0.5f * nv[j].x;
            o.x = (ux > 1.0f) ? 1.0f : 0.0f;
            ux  = (ux > 1.0f) ? 0.0f : ux;

            uy  = fmaf(0.5f, uy, xv[j].y) - 0.5f * nv[j].y;
            o.y = (uy > 1.0f) ? 1.0f : 0.0f;
            uy  = (uy > 1.0f) ? 0.0f : uy;

            uz  = fmaf(0.5f, uz, xv[j].z) - 0.5f * nv[j].z;
            o.z = (uz > 1.0f) ? 1.0f : 0.0f;
            uz  = (uz > 1.0f) ? 0.0f : uz;

            uw  = fmaf(0.5f, uw, xv[j].w) - 0.5f * nv[j].w;
            o.w = (uw > 1.0f) ? 1.0f : 0.0f;
            uw  = (uw > 1.0f) ? 0.0f : uw;

            __stcs(op + (t0 + j) * N4, o);
        }
    }
}

extern "C" void kernel_launch(void* const* d_in, const int* in_sizes, int n_in,
                              void* d_out, int out_size)
{
    const float4* x     = (const float4*)d_in[0];
    const float4* noise = (const float4*)d_in[1];
    float4*       out   = (float4*)d_out;

    const int total_threads = B * N4;                    // 262144
    const int tpb = 128;
    const int blocks = (total_threads + tpb - 1) / tpb;  // 2048

    lif_kernel<<<blocks, tpb>>>(x, noise, out);
}

// round 17
// speedup vs baseline: 1.0628x; 1.0190x over previous
#include <cuda_runtime.h>

// Noisy LIF spiking neuron scan — R14: probe burst depth CH=8 (R2 direction).
//   u = 0.5*u + x[t] - 0.5*noise[t] ; o = (u > 1) ; u = o ? 0 : u
//
// R13 confirmed the R2 config (float4, CH=4, tpb=128) reproducibly times
// 123.4-123.6us while all other configs time 127-130, despite mediocre ncu
// numbers: the burst-batched load pattern wins in the harness's graph-replay
// regime (ncu's flushed isolated capture mis-ranks it). This round tests
// whether the burst effect is monotone: CH=8 -> 16 front-batched LDG.128
// per chunk. If timed regresses, CH=4 is the peak and R2 becomes final.

static constexpr int B  = 16;
static constexpr int T  = 64;
static constexpr int N  = 65536;
static constexpr int N4 = N / 4;     // float4 lanes per (b, t) row
static constexpr int CH = 8;         // timesteps per load batch

__global__ __launch_bounds__(128) void lif_kernel(
    const float4* __restrict__ x,
    const float4* __restrict__ noise,
    float4* __restrict__ out)
{
    int idx = blockIdx.x * blockDim.x + threadIdx.x;   // 0 .. B*N4-1
    if (idx >= B * N4) return;

    int b  = idx / N4;
    int n4 = idx % N4;

    const size_t base = (size_t)b * T * N4 + n4;
    const float4* __restrict__ xp = x     + base;
    const float4* __restrict__ np = noise + base;
    float4*       __restrict__ op = out   + base;

    float ux = 0.f, uy = 0.f, uz = 0.f, uw = 0.f;

#pragma unroll
    for (int t0 = 0; t0 < T; t0 += CH) {
        float4 xv[CH], nv[CH];

        // Front-batch all loads for this chunk: 2*CH = 16 independent LDG.128.
#pragma unroll
        for (int j = 0; j < CH; j++) {
            xv[j] = __ldcs(xp + (t0 + j) * N4);
            nv[j] = __ldcs(np + (t0 + j) * N4);
        }

#pragma unroll
        for (int j = 0; j < CH; j++) {
            float4 o;

            ux  = fmaf(0.5f, ux, xv[j].x) - 0.5f * nv[j].x;
            o.x = (ux > 1.0f) ? 1.0f : 0.0f;
            ux  = (ux > 1.0f) ? 0.0f : ux;

            uy  = fmaf(0.5f, uy, xv[j].y) - 0.5f * nv[j].y;
            o.y = (uy > 1.0f) ? 1.0f : 0.0f;
            uy  = (uy > 1.0f) ? 0.0f : uy;

            uz  = fmaf(0.5f, uz, xv[j].z) - 0.5f * nv[j].z;
            o.z = (uz > 1.0f) ? 1.0f : 0.0f;
            uz  = (uz > 1.0f) ? 0.0f : uz;

            uw  = fmaf(0.5f, uw, xv[j].w) - 0.5f * nv[j].w;
            o.w = (uw > 1.0f) ? 1.0f : 0.0f;
            uw  = (uw > 1.0f) ? 0.0f : uw;

            __stcs(op + (t0 + j) * N4, o);
        }
    }
}

extern "C" void kernel_launch(void* const* d_in, const int* in_sizes, int n_in,
                              void* d_out, int out_size)
{
    const float4* x     = (const float4*)d_in[0];
    const float4* noise = (const float4*)d_in[1];
    float4*       out   = (float4*)d_out;

    const int total_threads = B * N4;                    // 262144
    const int tpb = 128;
    const int blocks = (total_threads + tpb - 1) / tpb;  // 2048

    lif_kernel<<<blocks, tpb>>>(x, noise, out);
}